// round 15
// baseline (speedup 1.0000x reference)
#include <cuda_runtime.h>
#include <cstdint>

// ---------------------------------------------------------------------------
// Problem constants
// ---------------------------------------------------------------------------
namespace {
constexpr int S    = 2048;   // tokens
constexpr int KD   = 2048;   // H (reduction dim)
constexpr int ND   = 6144;   // DQ + 2*DKV
constexpr int NQ   = 2048;   // DQ  (also DKV)
constexpr int NL   = 4;      // adapters
constexpr int TC   = 64;     // LoRA T columns (2*R)
constexpr int RNK  = 32;

constexpr int BM = 128, BN = 128, BK = 32;
constexpr int ASTR = 36;     // padded smem row stride for A tile (floats)
constexpr int BSTR = 136;    // padded smem row stride for B tile (floats)
constexpr int KTILES = KD / BK;   // 64
// smem: As[2][BM*ASTR] + Bs[2][BK*BSTR] + RWb[BK*BN] + RD[BK*BN]
constexpr int SMEM_MAIN =
    (2 * BM * ASTR + 2 * BK * BSTR + 2 * BK * BN) * (int)sizeof(float); // 104448 B
}

// Scratch (static device globals: no allocations allowed)
__device__ int   g_toklist[S];
__device__ int   g_off[NL + 1];
__device__ float g_T[S * TC];

// ---------------------------------------------------------------------------
// Helpers
// ---------------------------------------------------------------------------
__device__ __forceinline__ unsigned f2tf(float f) {
    unsigned u;
    asm("cvt.rna.tf32.f32 %0, %1;" : "=r"(u) : "f"(f));
    return u;
}

__device__ __forceinline__ void mma_tf32(float* d, const unsigned* a, const unsigned* b) {
    asm volatile(
        "mma.sync.aligned.m16n8k8.row.col.f32.tf32.tf32.f32 "
        "{%0,%1,%2,%3}, {%4,%5,%6,%7}, {%8,%9}, {%0,%1,%2,%3};"
        : "+f"(d[0]), "+f"(d[1]), "+f"(d[2]), "+f"(d[3])
        : "r"(a[0]), "r"(a[1]), "r"(a[2]), "r"(a[3]), "r"(b[0]), "r"(b[1]));
}

__device__ __forceinline__ void cp_async16(uint32_t sdst, const void* gsrc, int srcsize) {
    asm volatile("cp.async.ca.shared.global [%0], [%1], 16, %2;"
                 :: "r"(sdst), "l"(gsrc), "r"(srcsize));
}
__device__ __forceinline__ void cp_commit()  { asm volatile("cp.async.commit_group;"); }
__device__ __forceinline__ void cp_wait_all(){ asm volatile("cp.async.wait_group 0;"); }

// ---------------------------------------------------------------------------
// Kernel 1: stable group-by-adapter compaction of token ids
// ---------------------------------------------------------------------------
__global__ __launch_bounds__(256)
void group_kernel(const int* __restrict__ widx) {
    __shared__ int cnts[NL][256];
    __shared__ int gbase[NL];
    const int t = threadIdx.x;

    int loc[NL] = {0, 0, 0, 0};
    int l8[8];
#pragma unroll
    for (int j = 0; j < 8; j++) {
        l8[j] = widx[t * 8 + j];
        loc[l8[j]]++;
    }
#pragma unroll
    for (int l = 0; l < NL; l++) cnts[l][t] = loc[l];
    __syncthreads();

    if (t < NL) {                       // exclusive prefix over threads, per adapter
        int s = 0;
        for (int i = 0; i < 256; i++) { int v = cnts[t][i]; cnts[t][i] = s; s += v; }
        gbase[t] = s;                   // total for adapter t
    }
    __syncthreads();
    if (t == 0) {                       // exclusive prefix over adapters
        int s = 0;
        for (int l = 0; l < NL; l++) { int tot = gbase[l]; g_off[l] = s; gbase[l] = s; s += tot; }
        g_off[NL] = s;
    }
    __syncthreads();

    int pos[NL];
#pragma unroll
    for (int l = 0; l < NL; l++) pos[l] = gbase[l] + cnts[l][t];
#pragma unroll
    for (int j = 0; j < 8; j++) {
        int l = l8[j];
        g_toklist[pos[l]++] = t * 8 + j;
    }
}

// ---------------------------------------------------------------------------
// Kernel 2: T = x @ A[idx]   (per-group, gathered rows).  2048 x 64, K = 2048.
// grid.x = NL * 32 (64-row tiles), 256 threads.
// ---------------------------------------------------------------------------
__global__ __launch_bounds__(256)
void lora_a_kernel(const float* __restrict__ x, const float* __restrict__ A) {
    const int grp = blockIdx.x >> 5;
    const int mt  = blockIdx.x & 31;
    const int off = g_off[grp];
    const int cnt = g_off[grp + 1] - off;
    const int m0  = mt * 64;
    if (m0 >= cnt) return;

    __shared__ float xs[64][33];
    __shared__ float as_s[32][TC];

    const int tid = threadIdx.x;
    const int tx = tid & 31;      // output col (and col+32)
    const int ty = tid >> 5;      // output row block (8 rows each)

    int xtok[8];
#pragma unroll
    for (int j = 0; j < 8; j++) {
        int mi = m0 + (tid >> 5) + 8 * j;
        xtok[j] = (mi < cnt) ? g_toklist[off + mi] : -1;
    }

    const float* Ab = A + (size_t)grp * KD * TC;

    float acc[8][2];
#pragma unroll
    for (int i = 0; i < 8; i++) { acc[i][0] = 0.f; acc[i][1] = 0.f; }

    for (int k0 = 0; k0 < KD; k0 += 32) {
        __syncthreads();
#pragma unroll
        for (int j = 0; j < 8; j++) {
            int r  = (tid >> 5) + 8 * j;
            int kk = tid & 31;
            float v = 0.f;
            if (xtok[j] >= 0) v = x[(size_t)xtok[j] * KD + k0 + kk];
            xs[r][kk] = v;
        }
#pragma unroll
        for (int j = 0; j < 8; j++) {
            int r = (tid >> 6) + 4 * j;
            int c = tid & 63;
            as_s[r][c] = Ab[(size_t)(k0 + r) * TC + c];
        }
        __syncthreads();
#pragma unroll
        for (int kk = 0; kk < 32; kk++) {
            float b0 = as_s[kk][tx];
            float b1 = as_s[kk][tx + 32];
#pragma unroll
            for (int i = 0; i < 8; i++) {
                float a = xs[ty * 8 + i][kk];
                acc[i][0] += a * b0;
                acc[i][1] += a * b1;
            }
        }
    }

#pragma unroll
    for (int i = 0; i < 8; i++) {
        int mi = m0 + ty * 8 + i;
        if (mi < cnt) {
            int tk = g_toklist[off + mi];
            g_T[tk * TC + tx]      = acc[i][0];
            g_T[tk * TC + tx + 32] = acc[i][1];
        }
    }
}

// ---------------------------------------------------------------------------
// Kernel 3: main fused grouped GEMM (tf32 mma.sync)
//   out[rows_g] = X_g @ (W_base + (D_g - m_g)*s_g)  + T_g @ B_g  (LoRA K-ext)
// grid = (64 m-tiles fast, 48 n-tiles), 256 threads, 2 CTAs/SM.
// W routed raw through smem via cp.async; dequant pass is smem->reg->smem
// (no LDG->FFMA stalls in the main loop). A fed as raw fp32 (HW tf32 trunc).
// ---------------------------------------------------------------------------
__global__ __launch_bounds__(256, 2)
void main_gemm(const float* __restrict__ x,  const float* __restrict__ Wb,
               const float* __restrict__ Bq, const float* __restrict__ Bkv,
               const float* __restrict__ Dq, const float* __restrict__ Mq,
               const float* __restrict__ Sq, const float* __restrict__ Dkv,
               const float* __restrict__ Mkv,const float* __restrict__ Skv,
               float* __restrict__ out) {
    const int n0  = blockIdx.y * BN;
    const int grp = blockIdx.x >> 4;
    const int mt  = blockIdx.x & 15;
    const int off = g_off[grp];
    const int cnt = g_off[grp + 1] - off;
    const int m0  = mt * BM;
    if (m0 >= cnt) return;

    extern __shared__ float smem[];
    float* As  = smem;                          // [2][BM*ASTR]
    float* Bs  = smem + 2 * BM * ASTR;          // [2][BK*BSTR]
    float* RWb = Bs + 2 * BK * BSTR;            // [BK*BN] raw W_base
    float* RD  = RWb + BK * BN;                 // [BK*BN] raw DeltaW
    const uint32_t smem_u = (uint32_t)__cvta_generic_to_shared(smem);
    const uint32_t rwb_u  = (uint32_t)__cvta_generic_to_shared(RWb);
    const uint32_t rd_u   = (uint32_t)__cvta_generic_to_shared(RD);

    const int tid = threadIdx.x;

    // ---- x / T tile loader mapping: 4 float4 per thread ----
    const int xc = (tid & 7) * 4;           // k-col within tile
    int tok[4]; int xsz[4];
#pragma unroll
    for (int j = 0; j < 4; j++) {
        int r  = (tid >> 3) + 32 * j;
        int mi = m0 + r;
        bool v = mi < cnt;
        tok[j] = v ? g_toklist[off + mi] : 0;
        xsz[j] = v ? 16 : 0;
    }

    // ---- raw W cp.async mapping: row rr, 4 chunks c0+32*jj ----
    const int rr = tid >> 3;                // 0..31
    const int c0 = (tid & 7) * 4;           // float col base

    // ---- block-uniform segment pointers (BN=128 never straddles NQ bounds) ----
    const float *DL, *Msrc, *Ssrc;
    int dstr;
    if (n0 < NQ) {
        DL   = Dq + (size_t)grp * KD * NQ + n0;
        Msrc = Mq + (size_t)grp * 16 * NQ + n0;
        Ssrc = Sq + (size_t)grp * 16 * NQ + n0;
        dstr = NQ;
    } else {
        int c2 = n0 - NQ;
        DL   = Dkv + (size_t)grp * KD * 4096 + c2;
        Msrc = Mkv + (size_t)grp * 16 * 4096 + c2;
        Ssrc = Skv + (size_t)grp * 16 * 4096 + c2;
        dstr = 4096;
    }
    const float* WbL = Wb + n0;

    // ---- dequant mapping: rows wr0+8j, cols wc..wc+3 ----
    const int wr0 = tid >> 5;               // 0..7
    const int wc  = (tid & 31) * 4;         // 0..124

    // ---- warp / fragment mapping ----
    const int warp = tid >> 5;
    const int wm = warp >> 1, wn = warp & 1;      // 4 x 2 warps, warp tile 32x64
    const int lane = tid & 31;
    const int gid = lane >> 2, tg = lane & 3;

    float acc[2][8][4];
#pragma unroll
    for (int a = 0; a < 2; a++)
#pragma unroll
        for (int b = 0; b < 8; b++)
#pragma unroll
            for (int c = 0; c < 4; c++) acc[a][b][c] = 0.f;

    auto cpa_x = [&](int buf, int k0) {
#pragma unroll
        for (int j = 0; j < 4; j++) {
            int r = (tid >> 3) + 32 * j;
            cp_async16(smem_u + (uint32_t)(buf * BM * ASTR + r * ASTR + xc) * 4,
                       x + (size_t)tok[j] * KD + k0 + xc, xsz[j]);
        }
    };
    auto cpa_raw = [&](int k0) {
#pragma unroll
        for (int jj = 0; jj < 4; jj++) {
            int cf = c0 + 32 * jj;
            cp_async16(rwb_u + (uint32_t)(rr * BN + cf) * 4,
                       WbL + (size_t)(k0 + rr) * ND + cf, 16);
            cp_async16(rd_u + (uint32_t)(rr * BN + cf) * 4,
                       DL + (size_t)(k0 + rr) * dstr + cf, 16);
        }
    };
    auto dequant = [&](int bufB, const float4& m4, const float4& s4) {
#pragma unroll
        for (int j = 0; j < 4; j++) {
            int row = wr0 + 8 * j;
            float4 b4 = *(const float4*)&RWb[row * BN + wc];
            float4 d4 = *(const float4*)&RD[row * BN + wc];
            float4 o;
            o.x = __uint_as_float(f2tf(b4.x + (d4.x - m4.x) * s4.x));
            o.y = __uint_as_float(f2tf(b4.y + (d4.y - m4.y) * s4.y));
            o.z = __uint_as_float(f2tf(b4.z + (d4.z - m4.z) * s4.z));
            o.w = __uint_as_float(f2tf(b4.w + (d4.w - m4.w) * s4.w));
            *(float4*)&Bs[bufB * BK * BSTR + row * BSTR + wc] = o;
        }
    };
    auto compute = [&](int buf) {
        const float* Ab = As + buf * BM * ASTR;
        const float* Bb = Bs + buf * BK * BSTR;
#pragma unroll
        for (int k8 = 0; k8 < 4; k8++) {
            const int kk = k8 * 8;
            unsigned af[2][4];
#pragma unroll
            for (int ms = 0; ms < 2; ms++) {
                int r = wm * 32 + ms * 16 + gid;
                // raw fp32 bits: tensor HW truncates mantissa to tf32
                af[ms][0] = __float_as_uint(Ab[(r    ) * ASTR + kk + tg    ]);
                af[ms][1] = __float_as_uint(Ab[(r + 8) * ASTR + kk + tg    ]);
                af[ms][2] = __float_as_uint(Ab[(r    ) * ASTR + kk + tg + 4]);
                af[ms][3] = __float_as_uint(Ab[(r + 8) * ASTR + kk + tg + 4]);
            }
#pragma unroll
            for (int h = 0; h < 2; h++) {
                unsigned bf[4][2];
#pragma unroll
                for (int ns = 0; ns < 4; ns++) {
                    int c = wn * 64 + (h * 4 + ns) * 8 + gid;
                    bf[ns][0] = __float_as_uint(Bb[(kk + tg    ) * BSTR + c]);
                    bf[ns][1] = __float_as_uint(Bb[(kk + tg + 4) * BSTR + c]);
                }
#pragma unroll
                for (int ms = 0; ms < 2; ms++)
#pragma unroll
                    for (int ns = 0; ns < 4; ns++)
                        mma_tf32(acc[ms][h * 4 + ns], af[ms], &bf[ns][0]);
            }
        }
    };
    auto ms_load = [&](int kg, float4& m4, float4& s4) {
        m4 = *(const float4*)(Msrc + (size_t)kg * dstr + wc);
        s4 = *(const float4*)(Ssrc + (size_t)kg * dstr + wc);
    };

    // ---- prologue: stage tile 0, dequant it, stage tile 1 ----
    float4 m4, s4;
    cpa_x(0, 0);
    cpa_raw(0);
    cp_commit();
    ms_load(0, m4, s4);
    cp_wait_all();
    __syncthreads();
    dequant(0, m4, s4);
    __syncthreads();
    cpa_x(1, BK);
    cpa_raw(BK);
    cp_commit();

    // ---- main loop ----
#pragma unroll 1
    for (int kt = 0; kt < KTILES; kt++) {
        int kg_n = (kt + 1) >> 2;
        if (kg_n > 15) kg_n = 15;
        ms_load(kg_n, m4, s4);              // for tile kt+1; covered by compute
        compute(kt & 1);
        cp_wait_all();                      // raw(kt+1), x(kt+1) landed
        __syncthreads();
        if (kt + 1 < KTILES) dequant((kt + 1) & 1, m4, s4);
        __syncthreads();                    // raw reads done before re-fill
        if (kt + 2 < KTILES) {
            cpa_x(kt & 1, (kt + 2) * BK);
            cpa_raw((kt + 2) * BK);
            cp_commit();
        }
    }

    // ---- LoRA K-extension (32 extra k) for Q and K column ranges ----
    if (n0 < 2 * NQ) {
        const int sel = (n0 < NQ) ? 0 : 1;
#pragma unroll
        for (int j = 0; j < 4; j++) {
            int r = (tid >> 3) + 32 * j;
            cp_async16(smem_u + (uint32_t)(r * ASTR + xc) * 4,
                       g_T + (size_t)tok[j] * TC + sel * RNK + xc, xsz[j]);
        }
        cp_commit();
        const float* Bmat;
        int bstrg;
        if (sel == 0) { Bmat = Bq  + (size_t)grp * RNK * NQ   + n0 + wc;        bstrg = NQ;   }
        else          { Bmat = Bkv + (size_t)grp * RNK * 4096 + (n0 - NQ) + wc; bstrg = 4096; }
        float4 lreg[4];
#pragma unroll
        for (int j = 0; j < 4; j++) {
            int k = wr0 + 8 * j;
            float4 b4 = *(const float4*)(Bmat + (size_t)k * bstrg);
            lreg[j].x = __uint_as_float(f2tf(b4.x));
            lreg[j].y = __uint_as_float(f2tf(b4.y));
            lreg[j].z = __uint_as_float(f2tf(b4.z));
            lreg[j].w = __uint_as_float(f2tf(b4.w));
        }
#pragma unroll
        for (int j = 0; j < 4; j++)
            *(float4*)&Bs[(wr0 + 8 * j) * BSTR + wc] = lreg[j];
        cp_wait_all();
        __syncthreads();
        compute(0);
    }

    // ---- writeback (scattered by token id; full coverage, no RMW) ----
#pragma unroll
    for (int ms = 0; ms < 2; ms++) {
#pragma unroll
        for (int ns = 0; ns < 8; ns++) {
            int rbase = wm * 32 + ms * 16 + gid;
            int c = n0 + wn * 64 + ns * 8 + tg * 2;
            int mi = m0 + rbase;
            if (mi < cnt) {
                int t0 = g_toklist[off + mi];
                *(float2*)&out[(size_t)t0 * ND + c] =
                    make_float2(acc[ms][ns][0], acc[ms][ns][1]);
            }
            mi = m0 + rbase + 8;
            if (mi < cnt) {
                int t1 = g_toklist[off + mi];
                *(float2*)&out[(size_t)t1 * ND + c] =
                    make_float2(acc[ms][ns][2], acc[ms][ns][3]);
            }
        }
    }
}

// ---------------------------------------------------------------------------
// Launch
// ---------------------------------------------------------------------------
extern "C" void kernel_launch(void* const* d_in, const int* in_sizes, int n_in,
                              void* d_out, int out_size) {
    const float* x    = (const float*)d_in[0];
    const float* Wb   = (const float*)d_in[1];
    const float* A    = (const float*)d_in[2];
    const float* Bq   = (const float*)d_in[3];
    const float* Bkv  = (const float*)d_in[4];
    const float* Dq   = (const float*)d_in[5];
    const float* Mq   = (const float*)d_in[6];
    const float* Sq   = (const float*)d_in[7];
    const float* Dkv  = (const float*)d_in[8];
    const float* Mkv  = (const float*)d_in[9];
    const float* Skv  = (const float*)d_in[10];
    const int*   widx = (const int*)d_in[11];
    float* out = (float*)d_out;

    cudaFuncSetAttribute(main_gemm, cudaFuncAttributeMaxDynamicSharedMemorySize, SMEM_MAIN);

    group_kernel<<<1, 256>>>(widx);
    lora_a_kernel<<<NL * 32, 256>>>(x, A);
    main_gemm<<<dim3(NL * 16, ND / BN), 256, SMEM_MAIN>>>(
        x, Wb, Bq, Bkv, Dq, Mq, Sq, Dkv, Mkv, Skv, out);
}

// round 16
// speedup vs baseline: 1.1756x; 1.1756x over previous
#include <cuda_runtime.h>
#include <cstdint>

// ---------------------------------------------------------------------------
// Problem constants
// ---------------------------------------------------------------------------
namespace {
constexpr int S    = 2048;   // tokens
constexpr int KD   = 2048;   // H (reduction dim)
constexpr int ND   = 6144;   // DQ + 2*DKV
constexpr int NQ   = 2048;   // DQ  (also DKV)
constexpr int NL   = 4;      // adapters
constexpr int TC   = 64;     // LoRA T columns (2*R)
constexpr int RNK  = 32;

constexpr int BM = 128, BN = 128, BK = 32;
constexpr int ASTR = 36;     // padded smem row stride for A tile (floats)
constexpr int BSTR = 136;    // padded smem row stride for B tile (floats)
constexpr int KTILES = KD / BK;   // 64
constexpr int SMEM_MAIN = (2 * BM * ASTR + 2 * BK * BSTR) * (int)sizeof(float); // 71680 B
}

// Scratch (static device globals: no allocations allowed)
__device__ int   g_toklist[S];
__device__ int   g_off[NL + 1];
__device__ float g_T[S * TC];

// ---------------------------------------------------------------------------
// Helpers
// ---------------------------------------------------------------------------
__device__ __forceinline__ unsigned f2tf(float f) {
    unsigned u;
    asm("cvt.rna.tf32.f32 %0, %1;" : "=r"(u) : "f"(f));
    return u;
}

__device__ __forceinline__ void mma_tf32(float* d, const unsigned* a, const unsigned* b) {
    asm volatile(
        "mma.sync.aligned.m16n8k8.row.col.f32.tf32.tf32.f32 "
        "{%0,%1,%2,%3}, {%4,%5,%6,%7}, {%8,%9}, {%0,%1,%2,%3};"
        : "+f"(d[0]), "+f"(d[1]), "+f"(d[2]), "+f"(d[3])
        : "r"(a[0]), "r"(a[1]), "r"(a[2]), "r"(a[3]), "r"(b[0]), "r"(b[1]));
}

__device__ __forceinline__ void cp_async16(uint32_t sdst, const void* gsrc, int srcsize) {
    asm volatile("cp.async.ca.shared.global [%0], [%1], 16, %2;"
                 :: "r"(sdst), "l"(gsrc), "r"(srcsize));
}
__device__ __forceinline__ void cp_commit()  { asm volatile("cp.async.commit_group;"); }
__device__ __forceinline__ void cp_wait_all(){ asm volatile("cp.async.wait_group 0;"); }

// ---------------------------------------------------------------------------
// Kernel 1: stable group-by-adapter compaction of token ids
// ---------------------------------------------------------------------------
__global__ __launch_bounds__(256)
void group_kernel(const int* __restrict__ widx) {
    __shared__ int cnts[NL][256];
    __shared__ int gbase[NL];
    const int t = threadIdx.x;

    int loc[NL] = {0, 0, 0, 0};
    int l8[8];
#pragma unroll
    for (int j = 0; j < 8; j++) {
        l8[j] = widx[t * 8 + j];
        loc[l8[j]]++;
    }
#pragma unroll
    for (int l = 0; l < NL; l++) cnts[l][t] = loc[l];
    __syncthreads();

    if (t < NL) {                       // exclusive prefix over threads, per adapter
        int s = 0;
        for (int i = 0; i < 256; i++) { int v = cnts[t][i]; cnts[t][i] = s; s += v; }
        gbase[t] = s;                   // total for adapter t
    }
    __syncthreads();
    if (t == 0) {                       // exclusive prefix over adapters
        int s = 0;
        for (int l = 0; l < NL; l++) { int tot = gbase[l]; g_off[l] = s; gbase[l] = s; s += tot; }
        g_off[NL] = s;
    }
    __syncthreads();

    int pos[NL];
#pragma unroll
    for (int l = 0; l < NL; l++) pos[l] = gbase[l] + cnts[l][t];
#pragma unroll
    for (int j = 0; j < 8; j++) {
        int l = l8[j];
        g_toklist[pos[l]++] = t * 8 + j;
    }
}

// ---------------------------------------------------------------------------
// Kernel 2: T = x @ A[idx]   (per-group, gathered rows).  2048 x 64, K = 2048.
// grid.x = NL * 32 (64-row tiles), 256 threads.
// ---------------------------------------------------------------------------
__global__ __launch_bounds__(256)
void lora_a_kernel(const float* __restrict__ x, const float* __restrict__ A) {
    const int grp = blockIdx.x >> 5;
    const int mt  = blockIdx.x & 31;
    const int off = g_off[grp];
    const int cnt = g_off[grp + 1] - off;
    const int m0  = mt * 64;
    if (m0 >= cnt) return;

    __shared__ float xs[64][33];
    __shared__ float as_s[32][TC];

    const int tid = threadIdx.x;
    const int tx = tid & 31;      // output col (and col+32)
    const int ty = tid >> 5;      // output row block (8 rows each)

    int xtok[8];
#pragma unroll
    for (int j = 0; j < 8; j++) {
        int mi = m0 + (tid >> 5) + 8 * j;
        xtok[j] = (mi < cnt) ? g_toklist[off + mi] : -1;
    }

    const float* Ab = A + (size_t)grp * KD * TC;

    float acc[8][2];
#pragma unroll
    for (int i = 0; i < 8; i++) { acc[i][0] = 0.f; acc[i][1] = 0.f; }

    for (int k0 = 0; k0 < KD; k0 += 32) {
        __syncthreads();
#pragma unroll
        for (int j = 0; j < 8; j++) {
            int r  = (tid >> 5) + 8 * j;
            int kk = tid & 31;
            float v = 0.f;
            if (xtok[j] >= 0) v = x[(size_t)xtok[j] * KD + k0 + kk];
            xs[r][kk] = v;
        }
#pragma unroll
        for (int j = 0; j < 8; j++) {
            int r = (tid >> 6) + 4 * j;
            int c = tid & 63;
            as_s[r][c] = Ab[(size_t)(k0 + r) * TC + c];
        }
        __syncthreads();
#pragma unroll
        for (int kk = 0; kk < 32; kk++) {
            float b0 = as_s[kk][tx];
            float b1 = as_s[kk][tx + 32];
#pragma unroll
            for (int i = 0; i < 8; i++) {
                float a = xs[ty * 8 + i][kk];
                acc[i][0] += a * b0;
                acc[i][1] += a * b1;
            }
        }
    }

#pragma unroll
    for (int i = 0; i < 8; i++) {
        int mi = m0 + ty * 8 + i;
        if (mi < cnt) {
            int tk = g_toklist[off + mi];
            g_T[tk * TC + tx]      = acc[i][0];
            g_T[tk * TC + tx + 32] = acc[i][1];
        }
    }
}

// ---------------------------------------------------------------------------
// Kernel 3: main fused grouped GEMM (tf32 mma.sync)
//   out[rows_g] = X_g @ (W_base + (D_g - m_g)*s_g)  + T_g @ B_g  (LoRA K-ext)
// grid = (64 m-tiles fast, 48 n-tiles), 256 threads, 2 CTAs/SM.
// W LDGs issued BEFORE compute (raw in regs), dequant FFMA + STS AFTER
// compute -> LDG latency bridged by the MMA block. One barrier per k-tile.
// A fed as raw fp32 bits (HW tf32 truncation); W rna-converted.
// ---------------------------------------------------------------------------
__global__ __launch_bounds__(256, 2)
void main_gemm(const float* __restrict__ x,  const float* __restrict__ Wb,
               const float* __restrict__ Bq, const float* __restrict__ Bkv,
               const float* __restrict__ Dq, const float* __restrict__ Mq,
               const float* __restrict__ Sq, const float* __restrict__ Dkv,
               const float* __restrict__ Mkv,const float* __restrict__ Skv,
               float* __restrict__ out) {
    const int n0  = blockIdx.y * BN;
    const int grp = blockIdx.x >> 4;
    const int mt  = blockIdx.x & 15;
    const int off = g_off[grp];
    const int cnt = g_off[grp + 1] - off;
    const int m0  = mt * BM;
    if (m0 >= cnt) return;

    extern __shared__ float smem[];
    float* As = smem;                       // [2][BM*ASTR]
    float* Bs = smem + 2 * BM * ASTR;       // [2][BK*BSTR]
    const uint32_t smem_u = (uint32_t)__cvta_generic_to_shared(smem);

    const int tid = threadIdx.x;

    // ---- x / T tile loader mapping: 4 float4 per thread ----
    const int xc = (tid & 7) * 4;           // k-col within tile
    int tok[4]; int xsz[4];
#pragma unroll
    for (int j = 0; j < 4; j++) {
        int r  = (tid >> 3) + 32 * j;
        int mi = m0 + r;
        bool v = mi < cnt;
        tok[j] = v ? g_toklist[off + mi] : 0;
        xsz[j] = v ? 16 : 0;
    }

    // ---- W tile mapping: 4 float4 per thread (rows wr0+8j, col wc) ----
    const int wc   = (tid & 31) * 4;
    const int wcol = n0 + wc;               // global output col
    const int wr0  = tid >> 5;

    const float *Dp, *Mp, *Sp;
    int dstr;
    if (wcol < NQ) {
        Dp = Dq  + (size_t)grp * KD * NQ + wcol;
        Mp = Mq  + (size_t)grp * 16 * NQ + wcol;
        Sp = Sq  + (size_t)grp * 16 * NQ + wcol;
        dstr = NQ;
    } else {
        int c2 = wcol - NQ;
        Dp = Dkv + (size_t)grp * KD * 4096 + c2;
        Mp = Mkv + (size_t)grp * 16 * 4096 + c2;
        Sp = Skv + (size_t)grp * 16 * 4096 + c2;
        dstr = 4096;
    }
    const float* Wbp = Wb + wcol;

    // ---- warp / fragment mapping ----
    const int warp = tid >> 5;
    const int wm = warp >> 1, wn = warp & 1;      // 4 x 2 warps, warp tile 32x64
    const int lane = tid & 31;
    const int gid = lane >> 2, tg = lane & 3;

    float acc[2][8][4];
#pragma unroll
    for (int a = 0; a < 2; a++)
#pragma unroll
        for (int b = 0; b < 8; b++)
#pragma unroll
            for (int c = 0; c < 4; c++) acc[a][b][c] = 0.f;

    float4 b4r[4], d4r[4];                  // raw W, live across compute

    auto load_raw = [&](int k0) {
#pragma unroll
        for (int j = 0; j < 4; j++) {
            int k = k0 + wr0 + 8 * j;
            b4r[j] = *(const float4*)(Wbp + (size_t)k * ND);
            d4r[j] = *(const float4*)(Dp  + (size_t)k * dstr);
        }
    };
    auto dequant_sts = [&](int bufB, int kg) {
        float4 m4 = *(const float4*)(Mp + (size_t)kg * dstr);
        float4 s4 = *(const float4*)(Sp + (size_t)kg * dstr);
#pragma unroll
        for (int j = 0; j < 4; j++) {
            float4 o;
            o.x = __uint_as_float(f2tf(b4r[j].x + (d4r[j].x - m4.x) * s4.x));
            o.y = __uint_as_float(f2tf(b4r[j].y + (d4r[j].y - m4.y) * s4.y));
            o.z = __uint_as_float(f2tf(b4r[j].z + (d4r[j].z - m4.z) * s4.z));
            o.w = __uint_as_float(f2tf(b4r[j].w + (d4r[j].w - m4.w) * s4.w));
            *(float4*)&Bs[bufB * BK * BSTR + (wr0 + 8 * j) * BSTR + wc] = o;
        }
    };
    auto cpa_x = [&](int buf, int k0) {
#pragma unroll
        for (int j = 0; j < 4; j++) {
            int r = (tid >> 3) + 32 * j;
            cp_async16(smem_u + (uint32_t)(buf * BM * ASTR + r * ASTR + xc) * 4,
                       x + (size_t)tok[j] * KD + k0 + xc, xsz[j]);
        }
        cp_commit();
    };

    auto compute = [&](int buf) {
        const float* Ab = As + buf * BM * ASTR;
        const float* Bb = Bs + buf * BK * BSTR;
#pragma unroll
        for (int k8 = 0; k8 < 4; k8++) {
            const int kk = k8 * 8;
            unsigned af[2][4];
#pragma unroll
            for (int ms = 0; ms < 2; ms++) {
                int r = wm * 32 + ms * 16 + gid;
                // raw fp32 bits: tensor HW truncates mantissa to tf32
                af[ms][0] = __float_as_uint(Ab[(r    ) * ASTR + kk + tg    ]);
                af[ms][1] = __float_as_uint(Ab[(r + 8) * ASTR + kk + tg    ]);
                af[ms][2] = __float_as_uint(Ab[(r    ) * ASTR + kk + tg + 4]);
                af[ms][3] = __float_as_uint(Ab[(r + 8) * ASTR + kk + tg + 4]);
            }
            // split ns into 2 halves of 4 to cap live bf registers
#pragma unroll
            for (int h = 0; h < 2; h++) {
                unsigned bf[4][2];
#pragma unroll
                for (int ns = 0; ns < 4; ns++) {
                    int c = wn * 64 + (h * 4 + ns) * 8 + gid;
                    bf[ns][0] = __float_as_uint(Bb[(kk + tg    ) * BSTR + c]);
                    bf[ns][1] = __float_as_uint(Bb[(kk + tg + 4) * BSTR + c]);
                }
#pragma unroll
                for (int ms = 0; ms < 2; ms++)
#pragma unroll
                    for (int ns = 0; ns < 4; ns++)
                        mma_tf32(acc[ms][h * 4 + ns], af[ms], &bf[ns][0]);
            }
        }
    };

    // ---- prologue: B(0) built, x(0) staged, raw W(1) in flight ----
    cpa_x(0, 0);
    load_raw(0);
    dequant_sts(0, 0);          // one-time exposed LDG latency
    load_raw(BK);
    cp_wait_all();
    __syncthreads();

    // ---- main K loop ----
    int buf = 0;
#pragma unroll 1
    for (int kt = 0; kt < KTILES; kt++) {
        if (kt + 1 < KTILES) cpa_x(buf ^ 1, (kt + 1) * BK);
        compute(buf);                                   // covers raw(kt+1) LDGs
        if (kt + 1 < KTILES) dequant_sts(buf ^ 1, ((kt + 1) * BK) >> 7);
        if (kt + 2 < KTILES) load_raw((kt + 2) * BK);   // consumed after compute(kt+1)
        cp_wait_all();
        __syncthreads();
        buf ^= 1;
    }

    // ---- LoRA K-extension (32 extra k) for Q and K column ranges ----
    // (loop ends with buf back at 0; buffer 0 free after final barrier)
    if (n0 < 2 * NQ) {
        const int sel = (n0 < NQ) ? 0 : 1;
#pragma unroll
        for (int j = 0; j < 4; j++) {
            int r = (tid >> 3) + 32 * j;
            cp_async16(smem_u + (uint32_t)(r * ASTR + xc) * 4,
                       g_T + (size_t)tok[j] * TC + sel * RNK + xc, xsz[j]);
        }
        cp_commit();
        const float* Bmat;
        int bstrg;
        if (sel == 0) { Bmat = Bq  + (size_t)grp * RNK * NQ   + wcol;        bstrg = NQ;   }
        else          { Bmat = Bkv + (size_t)grp * RNK * 4096 + (wcol - NQ); bstrg = 4096; }
#pragma unroll
        for (int j = 0; j < 4; j++) {
            int k = wr0 + 8 * j;
            float4 b4 = *(const float4*)(Bmat + (size_t)k * bstrg);
            float4 o;
            o.x = __uint_as_float(f2tf(b4.x));
            o.y = __uint_as_float(f2tf(b4.y));
            o.z = __uint_as_float(f2tf(b4.z));
            o.w = __uint_as_float(f2tf(b4.w));
            *(float4*)&Bs[(wr0 + 8 * j) * BSTR + wc] = o;
        }
        cp_wait_all();
        __syncthreads();
        compute(0);
    }

    // ---- writeback (scattered by token id; full coverage, no RMW) ----
#pragma unroll
    for (int ms = 0; ms < 2; ms++) {
#pragma unroll
        for (int ns = 0; ns < 8; ns++) {
            int rbase = wm * 32 + ms * 16 + gid;
            int c = n0 + wn * 64 + ns * 8 + tg * 2;
            int mi = m0 + rbase;
            if (mi < cnt) {
                int t0 = g_toklist[off + mi];
                *(float2*)&out[(size_t)t0 * ND + c] =
                    make_float2(acc[ms][ns][0], acc[ms][ns][1]);
            }
            mi = m0 + rbase + 8;
            if (mi < cnt) {
                int t1 = g_toklist[off + mi];
                *(float2*)&out[(size_t)t1 * ND + c] =
                    make_float2(acc[ms][ns][2], acc[ms][ns][3]);
            }
        }
    }
}

// ---------------------------------------------------------------------------
// Launch
// ---------------------------------------------------------------------------
extern "C" void kernel_launch(void* const* d_in, const int* in_sizes, int n_in,
                              void* d_out, int out_size) {
    const float* x    = (const float*)d_in[0];
    const float* Wb   = (const float*)d_in[1];
    const float* A    = (const float*)d_in[2];
    const float* Bq   = (const float*)d_in[3];
    const float* Bkv  = (const float*)d_in[4];
    const float* Dq   = (const float*)d_in[5];
    const float* Mq   = (const float*)d_in[6];
    const float* Sq   = (const float*)d_in[7];
    const float* Dkv  = (const float*)d_in[8];
    const float* Mkv  = (const float*)d_in[9];
    const float* Skv  = (const float*)d_in[10];
    const int*   widx = (const int*)d_in[11];
    float* out = (float*)d_out;

    cudaFuncSetAttribute(main_gemm, cudaFuncAttributeMaxDynamicSharedMemorySize, SMEM_MAIN);

    group_kernel<<<1, 256>>>(widx);
    lora_a_kernel<<<NL * 32, 256>>>(x, A);
    main_gemm<<<dim3(NL * 16, ND / BN), 256, SMEM_MAIN>>>(
        x, Wb, Bq, Bkv, Dq, Mq, Sq, Dkv, Mkv, Skv, out);
}

// round 17
// speedup vs baseline: 1.2436x; 1.0579x over previous
#include <cuda_runtime.h>
#include <cstdint>

// ---------------------------------------------------------------------------
// Problem constants
// ---------------------------------------------------------------------------
namespace {
constexpr int S    = 2048;   // tokens
constexpr int KD   = 2048;   // H (reduction dim)
constexpr int ND   = 6144;   // DQ + 2*DKV
constexpr int NQ   = 2048;   // DQ  (also DKV)
constexpr int NL   = 4;      // adapters
constexpr int TC   = 64;     // LoRA T columns (2*R)
constexpr int RNK  = 32;

constexpr int BM = 128, BN = 128, BK = 32;
constexpr int ASTR = 36;     // padded smem row stride for A tile (floats)
constexpr int BSTR = 136;    // padded smem row stride for B tile (floats)
constexpr int KTILES = KD / BK;   // 64
constexpr int SMEM_MAIN = (2 * BM * ASTR + 2 * BK * BSTR) * (int)sizeof(float); // 71680 B
}

// Scratch (static device globals: no allocations allowed)
__device__ int   g_toklist[S];
__device__ int   g_off[NL + 1];
__device__ float g_T[S * TC];

// ---------------------------------------------------------------------------
// Helpers
// ---------------------------------------------------------------------------
__device__ __forceinline__ unsigned f2tf(float f) {
    unsigned u;
    asm("cvt.rna.tf32.f32 %0, %1;" : "=r"(u) : "f"(f));
    return u;
}

__device__ __forceinline__ void mma_tf32(float* d, const unsigned* a, const unsigned* b) {
    asm volatile(
        "mma.sync.aligned.m16n8k8.row.col.f32.tf32.tf32.f32 "
        "{%0,%1,%2,%3}, {%4,%5,%6,%7}, {%8,%9}, {%0,%1,%2,%3};"
        : "+f"(d[0]), "+f"(d[1]), "+f"(d[2]), "+f"(d[3])
        : "r"(a[0]), "r"(a[1]), "r"(a[2]), "r"(a[3]), "r"(b[0]), "r"(b[1]));
}

__device__ __forceinline__ void cp_async16(uint32_t sdst, const void* gsrc, int srcsize) {
    asm volatile("cp.async.ca.shared.global [%0], [%1], 16, %2;"
                 :: "r"(sdst), "l"(gsrc), "r"(srcsize));
}
__device__ __forceinline__ void cp_commit()  { asm volatile("cp.async.commit_group;"); }
__device__ __forceinline__ void cp_wait_all(){ asm volatile("cp.async.wait_group 0;"); }

// ---------------------------------------------------------------------------
// Kernel 1: stable group-by-adapter compaction of token ids
// ---------------------------------------------------------------------------
__global__ __launch_bounds__(256)
void group_kernel(const int* __restrict__ widx) {
    __shared__ int cnts[NL][256];
    __shared__ int gbase[NL];
    const int t = threadIdx.x;

    int loc[NL] = {0, 0, 0, 0};
    int l8[8];
#pragma unroll
    for (int j = 0; j < 8; j++) {
        l8[j] = widx[t * 8 + j];
        loc[l8[j]]++;
    }
#pragma unroll
    for (int l = 0; l < NL; l++) cnts[l][t] = loc[l];
    __syncthreads();

    if (t < NL) {                       // exclusive prefix over threads, per adapter
        int s = 0;
        for (int i = 0; i < 256; i++) { int v = cnts[t][i]; cnts[t][i] = s; s += v; }
        gbase[t] = s;                   // total for adapter t
    }
    __syncthreads();
    if (t == 0) {                       // exclusive prefix over adapters
        int s = 0;
        for (int l = 0; l < NL; l++) { int tot = gbase[l]; g_off[l] = s; gbase[l] = s; s += tot; }
        g_off[NL] = s;
    }
    __syncthreads();

    int pos[NL];
#pragma unroll
    for (int l = 0; l < NL; l++) pos[l] = gbase[l] + cnts[l][t];
#pragma unroll
    for (int j = 0; j < 8; j++) {
        int l = l8[j];
        g_toklist[pos[l]++] = t * 8 + j;
    }
}

// ---------------------------------------------------------------------------
// Kernel 2: T = x @ A[idx]   (per-group, gathered rows).  2048 x 64, K = 2048.
// 32-row tiles -> grid.x = NL * 64 = 256 blocks (~2/SM, 4 warps/SMSP).
// ---------------------------------------------------------------------------
__global__ __launch_bounds__(256)
void lora_a_kernel(const float* __restrict__ x, const float* __restrict__ A) {
    const int grp = blockIdx.x >> 6;
    const int mt  = blockIdx.x & 63;
    const int off = g_off[grp];
    const int cnt = g_off[grp + 1] - off;
    const int m0  = mt * 32;
    if (m0 >= cnt) return;

    __shared__ float xs[32][33];
    __shared__ float as_s[32][TC];

    const int tid = threadIdx.x;
    const int tx = tid & 31;      // output col (and col+32)
    const int ty = tid >> 5;      // row block: rows ty*4 .. ty*4+3

    int xtok[4];
#pragma unroll
    for (int j = 0; j < 4; j++) {
        int mi = m0 + (tid >> 5) + 8 * j;
        xtok[j] = (mi < cnt) ? g_toklist[off + mi] : -1;
    }

    const float* Ab = A + (size_t)grp * KD * TC;

    float acc[4][2];
#pragma unroll
    for (int i = 0; i < 4; i++) { acc[i][0] = 0.f; acc[i][1] = 0.f; }

    for (int k0 = 0; k0 < KD; k0 += 32) {
        __syncthreads();
#pragma unroll
        for (int j = 0; j < 4; j++) {
            int r  = (tid >> 5) + 8 * j;
            int kk = tid & 31;
            float v = 0.f;
            if (xtok[j] >= 0) v = x[(size_t)xtok[j] * KD + k0 + kk];
            xs[r][kk] = v;
        }
#pragma unroll
        for (int j = 0; j < 8; j++) {
            int r = (tid >> 6) + 4 * j;
            int c = tid & 63;
            as_s[r][c] = Ab[(size_t)(k0 + r) * TC + c];
        }
        __syncthreads();
#pragma unroll
        for (int kk = 0; kk < 32; kk++) {
            float b0 = as_s[kk][tx];
            float b1 = as_s[kk][tx + 32];
#pragma unroll
            for (int i = 0; i < 4; i++) {
                float a = xs[ty * 4 + i][kk];
                acc[i][0] += a * b0;
                acc[i][1] += a * b1;
            }
        }
    }

#pragma unroll
    for (int i = 0; i < 4; i++) {
        int mi = m0 + ty * 4 + i;
        if (mi < cnt) {
            int tk = g_toklist[off + mi];
            g_T[tk * TC + tx]      = acc[i][0];
            g_T[tk * TC + tx + 32] = acc[i][1];
        }
    }
}

// ---------------------------------------------------------------------------
// Kernel 3: main fused grouped GEMM (tf32 mma.sync)  -- R14 configuration
//   out[rows_g] = X_g @ (W_base + (D_g - m_g)*s_g)  + T_g @ B_g  (LoRA K-ext)
// grid = (64 m-tiles fast, 48 n-tiles), 256 threads, 2 CTAs/SM.
// A fragments fed as raw fp32 bits (HW truncates to tf32); W rna-converted.
// ---------------------------------------------------------------------------
__global__ __launch_bounds__(256, 2)
void main_gemm(const float* __restrict__ x,  const float* __restrict__ Wb,
               const float* __restrict__ Bq, const float* __restrict__ Bkv,
               const float* __restrict__ Dq, const float* __restrict__ Mq,
               const float* __restrict__ Sq, const float* __restrict__ Dkv,
               const float* __restrict__ Mkv,const float* __restrict__ Skv,
               float* __restrict__ out) {
    const int n0  = blockIdx.y * BN;
    const int grp = blockIdx.x >> 4;
    const int mt  = blockIdx.x & 15;
    const int off = g_off[grp];
    const int cnt = g_off[grp + 1] - off;
    const int m0  = mt * BM;
    if (m0 >= cnt) return;

    extern __shared__ float smem[];
    float* As = smem;                       // [2][BM*ASTR]
    float* Bs = smem + 2 * BM * ASTR;       // [2][BK*BSTR]
    const uint32_t smem_u = (uint32_t)__cvta_generic_to_shared(smem);

    const int tid = threadIdx.x;

    // ---- x / T tile loader mapping: 4 float4 per thread ----
    const int xc = (tid & 7) * 4;           // k-col within tile
    int tok[4]; int xsz[4];
#pragma unroll
    for (int j = 0; j < 4; j++) {
        int r  = (tid >> 3) + 32 * j;
        int mi = m0 + r;
        bool v = mi < cnt;
        tok[j] = v ? g_toklist[off + mi] : 0;
        xsz[j] = v ? 16 : 0;
    }

    // ---- W tile mapping: 4 float4 per thread (rows wr0+8j, col wc) ----
    const int wc   = (tid & 31) * 4;
    const int wcol = n0 + wc;               // global output col
    const int wr0  = tid >> 5;

    const float *Dp, *Mp, *Sp;
    int dstr;
    if (wcol < NQ) {
        Dp = Dq  + (size_t)grp * KD * NQ + wcol;
        Mp = Mq  + (size_t)grp * 16 * NQ + wcol;
        Sp = Sq  + (size_t)grp * 16 * NQ + wcol;
        dstr = NQ;
    } else {
        int c2 = wcol - NQ;
        Dp = Dkv + (size_t)grp * KD * 4096 + c2;
        Mp = Mkv + (size_t)grp * 16 * 4096 + c2;
        Sp = Skv + (size_t)grp * 16 * 4096 + c2;
        dstr = 4096;
    }
    const float* Wbp = Wb + wcol;

    // ---- warp / fragment mapping ----
    const int warp = tid >> 5;
    const int wm = warp >> 1, wn = warp & 1;      // 4 x 2 warps, warp tile 32x64
    const int lane = tid & 31;
    const int gid = lane >> 2, tg = lane & 3;

    float acc[2][8][4];
#pragma unroll
    for (int a = 0; a < 2; a++)
#pragma unroll
        for (int b = 0; b < 8; b++)
#pragma unroll
            for (int c = 0; c < 4; c++) acc[a][b][c] = 0.f;

    float4 wreg[4];

    auto load_w = [&](int k0) {
        int kg = (k0 >> 7);                     // 128-group (constant over a 32-tile)
        float4 m4 = *(const float4*)(Mp + (size_t)kg * dstr);
        float4 s4 = *(const float4*)(Sp + (size_t)kg * dstr);
#pragma unroll
        for (int j = 0; j < 4; j++) {
            int k = k0 + wr0 + 8 * j;
            float4 b4 = *(const float4*)(Wbp + (size_t)k * ND);
            float4 d4 = *(const float4*)(Dp  + (size_t)k * dstr);
            float vx = b4.x + (d4.x - m4.x) * s4.x;
            float vy = b4.y + (d4.y - m4.y) * s4.y;
            float vz = b4.z + (d4.z - m4.z) * s4.z;
            float vw = b4.w + (d4.w - m4.w) * s4.w;
            // store pre-converted tf32 bit patterns (rna) for the B operand
            wreg[j].x = __uint_as_float(f2tf(vx));
            wreg[j].y = __uint_as_float(f2tf(vy));
            wreg[j].z = __uint_as_float(f2tf(vz));
            wreg[j].w = __uint_as_float(f2tf(vw));
        }
    };
    auto sts_w = [&](int buf) {
#pragma unroll
        for (int j = 0; j < 4; j++)
            *(float4*)&Bs[buf * BK * BSTR + (wr0 + 8 * j) * BSTR + wc] = wreg[j];
    };
    auto cpa_x = [&](int buf, int k0) {
#pragma unroll
        for (int j = 0; j < 4; j++) {
            int r = (tid >> 3) + 32 * j;
            cp_async16(smem_u + (uint32_t)(buf * BM * ASTR + r * ASTR + xc) * 4,
                       x + (size_t)tok[j] * KD + k0 + xc, xsz[j]);
        }
        cp_commit();
    };

    auto compute = [&](int buf) {
        const float* Ab = As + buf * BM * ASTR;
        const float* Bb = Bs + buf * BK * BSTR;
#pragma unroll
        for (int k8 = 0; k8 < 4; k8++) {
            const int kk = k8 * 8;
            unsigned af[2][4];
#pragma unroll
            for (int ms = 0; ms < 2; ms++) {
                int r = wm * 32 + ms * 16 + gid;
                // raw fp32 bits: tensor HW truncates mantissa to tf32
                af[ms][0] = __float_as_uint(Ab[(r    ) * ASTR + kk + tg    ]);
                af[ms][1] = __float_as_uint(Ab[(r + 8) * ASTR + kk + tg    ]);
                af[ms][2] = __float_as_uint(Ab[(r    ) * ASTR + kk + tg + 4]);
                af[ms][3] = __float_as_uint(Ab[(r + 8) * ASTR + kk + tg + 4]);
            }
            // split ns into 2 halves of 4 to cap live bf registers
#pragma unroll
            for (int h = 0; h < 2; h++) {
                unsigned bf[4][2];
#pragma unroll
                for (int ns = 0; ns < 4; ns++) {
                    int c = wn * 64 + (h * 4 + ns) * 8 + gid;
                    bf[ns][0] = __float_as_uint(Bb[(kk + tg    ) * BSTR + c]);
                    bf[ns][1] = __float_as_uint(Bb[(kk + tg + 4) * BSTR + c]);
                }
#pragma unroll
                for (int ms = 0; ms < 2; ms++)
#pragma unroll
                    for (int ns = 0; ns < 4; ns++)
                        mma_tf32(acc[ms][h * 4 + ns], af[ms], &bf[ns][0]);
            }
        }
    };

    // ---- main K loop, double-buffered ----
    cpa_x(0, 0);
    load_w(0);
    int buf = 0;
#pragma unroll 1
    for (int kt = 0; kt < KTILES; kt++) {
        sts_w(buf);
        cp_wait_all();
        __syncthreads();
        if (kt + 1 < KTILES) {
            cpa_x(buf ^ 1, (kt + 1) * BK);
            load_w((kt + 1) * BK);
        }
        compute(buf);
        buf ^= 1;
    }

    // ---- LoRA K-extension (32 extra k) for Q and K column ranges ----
    // (KTILES even -> last main-loop compute used buffer 1; buffer 0 is free)
    if (n0 < 2 * NQ) {
        const int sel = (n0 < NQ) ? 0 : 1;
#pragma unroll
        for (int j = 0; j < 4; j++) {
            int r = (tid >> 3) + 32 * j;
            cp_async16(smem_u + (uint32_t)(r * ASTR + xc) * 4,
                       g_T + (size_t)tok[j] * TC + sel * RNK + xc, xsz[j]);
        }
        cp_commit();
        const float* Bmat;
        int bstrg;
        if (sel == 0) { Bmat = Bq  + (size_t)grp * RNK * NQ   + wcol;        bstrg = NQ;   }
        else          { Bmat = Bkv + (size_t)grp * RNK * 4096 + (wcol - NQ); bstrg = 4096; }
#pragma unroll
        for (int j = 0; j < 4; j++) {
            int k = wr0 + 8 * j;
            float4 b4 = *(const float4*)(Bmat + (size_t)k * bstrg);
            wreg[j].x = __uint_as_float(f2tf(b4.x));
            wreg[j].y = __uint_as_float(f2tf(b4.y));
            wreg[j].z = __uint_as_float(f2tf(b4.z));
            wreg[j].w = __uint_as_float(f2tf(b4.w));
        }
        sts_w(0);
        cp_wait_all();
        __syncthreads();
        compute(0);
    }

    // ---- writeback (scattered by token id; full coverage, no RMW) ----
#pragma unroll
    for (int ms = 0; ms < 2; ms++) {
#pragma unroll
        for (int ns = 0; ns < 8; ns++) {
            int rbase = wm * 32 + ms * 16 + gid;
            int c = n0 + wn * 64 + ns * 8 + tg * 2;
            int mi = m0 + rbase;
            if (mi < cnt) {
                int t0 = g_toklist[off + mi];
                *(float2*)&out[(size_t)t0 * ND + c] =
                    make_float2(acc[ms][ns][0], acc[ms][ns][1]);
            }
            mi = m0 + rbase + 8;
            if (mi < cnt) {
                int t1 = g_toklist[off + mi];
                *(float2*)&out[(size_t)t1 * ND + c] =
                    make_float2(acc[ms][ns][2], acc[ms][ns][3]);
            }
        }
    }
}

// ---------------------------------------------------------------------------
// Launch
// ---------------------------------------------------------------------------
extern "C" void kernel_launch(void* const* d_in, const int* in_sizes, int n_in,
                              void* d_out, int out_size) {
    const float* x    = (const float*)d_in[0];
    const float* Wb   = (const float*)d_in[1];
    const float* A    = (const float*)d_in[2];
    const float* Bq   = (const float*)d_in[3];
    const float* Bkv  = (const float*)d_in[4];
    const float* Dq   = (const float*)d_in[5];
    const float* Mq   = (const float*)d_in[6];
    const float* Sq   = (const float*)d_in[7];
    const float* Dkv  = (const float*)d_in[8];
    const float* Mkv  = (const float*)d_in[9];
    const float* Skv  = (const float*)d_in[10];
    const int*   widx = (const int*)d_in[11];
    float* out = (float*)d_out;

    cudaFuncSetAttribute(main_gemm, cudaFuncAttributeMaxDynamicSharedMemorySize, SMEM_MAIN);

    group_kernel<<<1, 256>>>(widx);
    lora_a_kernel<<<NL * 64, 256>>>(x, A);
    main_gemm<<<dim3(NL * 16, ND / BN), 256, SMEM_MAIN>>>(
        x, Wb, Bq, Bkv, Dq, Mq, Sq, Dkv, Mkv, Skv, out);
}